// round 11
// baseline (speedup 1.0000x reference)
#include <cuda_runtime.h>
#include <cstdint>

#define Bq 32
#define Sq 256
#define Eq 256
#define Hq 512
#define Gq 2048          // 4*H
#define M_TOT (Bq * Sq)  // 8192

#define SCAN_NCTA 128
#define SCAN_TPB  256
#define HP 132           // hsh row pad (floats)
#define WS 516           // Wsh row stride (floats)
#define NGEMM 1024       // co-scheduled gemm tiles (64 m-tiles x 16 n-tiles)

#define SCAN_SMEM_FLOATS (64 * WS + 8 * HP + 8 * 64 * 9 + 128)
#define SCAN_SMEM_BYTES  (SCAN_SMEM_FLOATS * 4)

typedef unsigned long long ull;

#define FMA2(acc, a, b) \
    asm("fma.rn.f32x2 %0, %1, %2, %0;" : "+l"(acc) : "l"(a), "l"(b))
#define DUP2(d, s) \
    asm("mov.b64 %0, {%1, %1};" : "=l"(d) : "f"(s))
#define UNPK2(lo, hi, v) \
    asm("mov.b64 {%0, %1}, %2;" : "=f"(lo), "=f"(hi) : "l"(v))

__device__ __forceinline__ float fsigmoid(float x) {
    return __fdividef(1.f, 1.f + __expf(-x));
}
__device__ __forceinline__ float ftanh(float x) {
    float e = __expf(2.f * x);
    return 1.f - __fdividef(2.f, e + 1.f);
}

// ---------------- device scratch (static, no allocation) ----------------
__device__ float g_gxA[M_TOT * Gq];      // gx ping
__device__ float g_gxB[M_TOT * Gq];      // gx pong
__device__ float g_io0[M_TOT * Hq];
__device__ float g_io1[M_TOT * Hq];
__device__ float g_h[2][Bq * Hq];
__device__ unsigned g_flagsL[4][SCAN_NCTA * 32];  // per-layer, 128B-padded slots

// ---------------- standalone layer-0 GEMM (also zeroes ALL flags) --------
__global__ void __launch_bounds__(256, 2) gemm_kernel(
    const float* __restrict__ A, const float* __restrict__ W,
    const float* __restrict__ bih, const float* __restrict__ bhh,
    float* __restrict__ C, int K)
{
    __shared__ float As[2][8][128];
    __shared__ float Bs[2][8][128];
    const int tid = threadIdx.x;

    // zero all layer flags once per replay (stream-ordered before co-kernels)
    if (blockIdx.x == 0 && blockIdx.y == 0) {
        unsigned* f = &g_flagsL[0][0];
        for (int i = tid; i < 4 * SCAN_NCTA * 32; i += 256) f[i] = 0u;
    }

    const int m0 = blockIdx.y * 128;
    const int n0 = blockIdx.x * 128;
    const int lr = tid >> 1;
    const int lk = (tid & 1) * 4;
    const int tx = tid & 15;
    const int ty = tid >> 4;

    ull acc2[8][4];
#pragma unroll
    for (int i = 0; i < 8; ++i)
#pragma unroll
        for (int j = 0; j < 4; ++j) acc2[i][j] = 0ull;

    const float* Ap = A + (size_t)(m0 + lr) * K + lk;
    const float* Wp = W + (size_t)(n0 + lr) * K + lk;
    float4 pa = *reinterpret_cast<const float4*>(Ap);
    float4 pb = *reinterpret_cast<const float4*>(Wp);

    As[0][lk + 0][lr] = pa.x; As[0][lk + 1][lr] = pa.y;
    As[0][lk + 2][lr] = pa.z; As[0][lk + 3][lr] = pa.w;
    Bs[0][lk + 0][lr] = pb.x; Bs[0][lk + 1][lr] = pb.y;
    Bs[0][lk + 2][lr] = pb.z; Bs[0][lk + 3][lr] = pb.w;
    __syncthreads();

    const int nk = K >> 3;
    for (int kt = 0; kt < nk; ++kt) {
        const int buf = kt & 1;
        if (kt + 1 < nk) {
            pa = *reinterpret_cast<const float4*>(Ap + (kt + 1) * 8);
            pb = *reinterpret_cast<const float4*>(Wp + (kt + 1) * 8);
        }
#pragma unroll
        for (int kk = 0; kk < 8; ++kk) {
            float4 a0 = *reinterpret_cast<const float4*>(&As[buf][kk][ty * 4]);
            float4 a1 = *reinterpret_cast<const float4*>(&As[buf][kk][64 + ty * 4]);
            ulonglong2 bb0 = *reinterpret_cast<const ulonglong2*>(&Bs[buf][kk][tx * 4]);
            ulonglong2 bb1 = *reinterpret_cast<const ulonglong2*>(&Bs[buf][kk][64 + tx * 4]);
            float am[8] = {a0.x, a0.y, a0.z, a0.w, a1.x, a1.y, a1.z, a1.w};
            ull bp0 = bb0.x, bp1 = bb0.y, bp2 = bb1.x, bp3 = bb1.y;
#pragma unroll
            for (int i = 0; i < 8; ++i) {
                ull a2; DUP2(a2, am[i]);
                FMA2(acc2[i][0], a2, bp0);
                FMA2(acc2[i][1], a2, bp1);
                FMA2(acc2[i][2], a2, bp2);
                FMA2(acc2[i][3], a2, bp3);
            }
        }
        if (kt + 1 < nk) {
            const int nb = buf ^ 1;
            As[nb][lk + 0][lr] = pa.x; As[nb][lk + 1][lr] = pa.y;
            As[nb][lk + 2][lr] = pa.z; As[nb][lk + 3][lr] = pa.w;
            Bs[nb][lk + 0][lr] = pb.x; Bs[nb][lk + 1][lr] = pb.y;
            Bs[nb][lk + 2][lr] = pb.z; Bs[nb][lk + 3][lr] = pb.w;
            __syncthreads();
        }
    }

    float acc[8][8];
#pragma unroll
    for (int i = 0; i < 8; ++i)
#pragma unroll
        for (int j = 0; j < 4; ++j)
            UNPK2(acc[i][2 * j], acc[i][2 * j + 1], acc2[i][j]);

    const int nc0 = n0 + tx * 4;
    const int nc1 = n0 + 64 + tx * 4;
    float bs0[4], bs1[4];
#pragma unroll
    for (int j = 0; j < 4; ++j) {
        bs0[j] = bih[nc0 + j] + bhh[nc0 + j];
        bs1[j] = bih[nc1 + j] + bhh[nc1 + j];
    }
#pragma unroll
    for (int i = 0; i < 8; ++i) {
        int m = m0 + ((i < 4) ? (ty * 4 + i) : (64 + ty * 4 + i - 4));
        float4 v0, v1;
        v0.x = acc[i][0] + bs0[0]; v0.y = acc[i][1] + bs0[1];
        v0.z = acc[i][2] + bs0[2]; v0.w = acc[i][3] + bs0[3];
        v1.x = acc[i][4] + bs1[0]; v1.y = acc[i][5] + bs1[1];
        v1.z = acc[i][6] + bs1[2]; v1.w = acc[i][7] + bs1[3];
        *reinterpret_cast<float4*>(C + (size_t)m * Gq + nc0) = v0;
        *reinterpret_cast<float4*>(C + (size_t)m * Gq + nc1) = v1;
    }
}

// ============== co-kernel: scan(layer) + flag-gated gemm(layer+1) ========
// bids 0..127: persistent scan CTAs (wave-1 resident, one per SM).
// bids 128+ : gemm tiles of NEXT layer's input GEMM; each polls scan
// progress flags (>= s0+129 covers out rows [s0, s0+128)) before running.
__global__ void __launch_bounds__(SCAN_TPB) scan_gemm_kernel(
    const float* __restrict__ gx,     // [b][s][2048]  this layer's gates
    const float* __restrict__ Whh,    // [2048][512]   this layer
    float* __restrict__ out,          // [b][s][512]   this layer's output
    int layer,
    const float* __restrict__ Wn,     // next layer Wih [2048][512] (or null)
    const float* __restrict__ bihn, const float* __restrict__ bhhn,
    float* __restrict__ gxn)          // next layer gx out
{
    extern __shared__ float sm[];
    const int tid = threadIdx.x;

    if (blockIdx.x >= SCAN_NCTA) {
        // ---------------- gemm role ----------------
        float* AsF = sm;               // [2][8][128]
        float* BsF = sm + 2048;        // [2][8][128]
        const int g  = blockIdx.x - SCAN_NCTA;
        const int s0 = (g < 512) ? 0 : 128;
        const int gg = g & 511;
        const int b  = gg >> 4;
        const int m0 = b * 256 + s0;
        const int n0 = (gg & 15) * 128;
        const int group = b >> 3;
        const unsigned target = (unsigned)(s0 + 129);

        if (tid < 32) {
            const unsigned* f = &g_flagsL[layer][(group * 32 + tid) * 32];
            unsigned v;
            do {
                asm volatile("ld.acquire.gpu.global.u32 %0, [%1];"
                             : "=r"(v) : "l"(f));
            } while (__all_sync(0xffffffffu, v >= target) == 0);
        }
        __syncthreads();

        const int K = Hq;              // 512
        const int lr = tid >> 1;
        const int lk = (tid & 1) * 4;
        const int tx = tid & 15;
        const int ty = tid >> 4;

        ull acc2[8][4];
#pragma unroll
        for (int i = 0; i < 8; ++i)
#pragma unroll
            for (int j = 0; j < 4; ++j) acc2[i][j] = 0ull;

        const float* Ap = out + (size_t)(m0 + lr) * K + lk;   // A = this layer's out
        const float* Wp = Wn + (size_t)(n0 + lr) * K + lk;
        float4 pa = *reinterpret_cast<const float4*>(Ap);
        float4 pb = *reinterpret_cast<const float4*>(Wp);

#define ASG(bf, r, c) AsF[(bf) * 1024 + (r) * 128 + (c)]
#define BSG(bf, r, c) BsF[(bf) * 1024 + (r) * 128 + (c)]
        ASG(0, lk + 0, lr) = pa.x; ASG(0, lk + 1, lr) = pa.y;
        ASG(0, lk + 2, lr) = pa.z; ASG(0, lk + 3, lr) = pa.w;
        BSG(0, lk + 0, lr) = pb.x; BSG(0, lk + 1, lr) = pb.y;
        BSG(0, lk + 2, lr) = pb.z; BSG(0, lk + 3, lr) = pb.w;
        __syncthreads();

        const int nk = K >> 3;
        for (int kt = 0; kt < nk; ++kt) {
            const int buf = kt & 1;
            if (kt + 1 < nk) {
                pa = *reinterpret_cast<const float4*>(Ap + (kt + 1) * 8);
                pb = *reinterpret_cast<const float4*>(Wp + (kt + 1) * 8);
            }
#pragma unroll
            for (int kk = 0; kk < 8; ++kk) {
                float4 a0 = *reinterpret_cast<const float4*>(&ASG(buf, kk, ty * 4));
                float4 a1 = *reinterpret_cast<const float4*>(&ASG(buf, kk, 64 + ty * 4));
                ulonglong2 bb0 = *reinterpret_cast<const ulonglong2*>(&BSG(buf, kk, tx * 4));
                ulonglong2 bb1 = *reinterpret_cast<const ulonglong2*>(&BSG(buf, kk, 64 + tx * 4));
                float am[8] = {a0.x, a0.y, a0.z, a0.w, a1.x, a1.y, a1.z, a1.w};
                ull bp0 = bb0.x, bp1 = bb0.y, bp2 = bb1.x, bp3 = bb1.y;
#pragma unroll
                for (int i = 0; i < 8; ++i) {
                    ull a2; DUP2(a2, am[i]);
                    FMA2(acc2[i][0], a2, bp0);
                    FMA2(acc2[i][1], a2, bp1);
                    FMA2(acc2[i][2], a2, bp2);
                    FMA2(acc2[i][3], a2, bp3);
                }
            }
            if (kt + 1 < nk) {
                const int nb = buf ^ 1;
                ASG(nb, lk + 0, lr) = pa.x; ASG(nb, lk + 1, lr) = pa.y;
                ASG(nb, lk + 2, lr) = pa.z; ASG(nb, lk + 3, lr) = pa.w;
                BSG(nb, lk + 0, lr) = pb.x; BSG(nb, lk + 1, lr) = pb.y;
                BSG(nb, lk + 2, lr) = pb.z; BSG(nb, lk + 3, lr) = pb.w;
                __syncthreads();
            }
        }
#undef ASG
#undef BSG

        float acc[8][8];
#pragma unroll
        for (int i = 0; i < 8; ++i)
#pragma unroll
            for (int j = 0; j < 4; ++j)
                UNPK2(acc[i][2 * j], acc[i][2 * j + 1], acc2[i][j]);

        const int nc0 = n0 + tx * 4;
        const int nc1 = n0 + 64 + tx * 4;
        float bs0[4], bs1[4];
#pragma unroll
        for (int j = 0; j < 4; ++j) {
            bs0[j] = bihn[nc0 + j] + bhhn[nc0 + j];
            bs1[j] = bihn[nc1 + j] + bhhn[nc1 + j];
        }
#pragma unroll
        for (int i = 0; i < 8; ++i) {
            int m = m0 + ((i < 4) ? (ty * 4 + i) : (64 + ty * 4 + i - 4));
            float4 v0, v1;
            v0.x = acc[i][0] + bs0[0]; v0.y = acc[i][1] + bs0[1];
            v0.z = acc[i][2] + bs0[2]; v0.w = acc[i][3] + bs0[3];
            v1.x = acc[i][4] + bs1[0]; v1.y = acc[i][5] + bs1[1];
            v1.z = acc[i][6] + bs1[2]; v1.w = acc[i][7] + bs1[3];
            *reinterpret_cast<float4*>(gxn + (size_t)m * Gq + nc0) = v0;
            *reinterpret_cast<float4*>(gxn + (size_t)m * Gq + nc1) = v1;
        }
        return;
    }

    // ---------------- scan role (R9-proven, per-layer flags) ----------------
    float* Wsh  = sm;                      // 64 * WS
    float* hsh  = Wsh + 64 * WS;           // 8 * HP
    float* part = hsh + 8 * HP;            // 8 * 64 * 9
    float* csh  = part + 8 * 64 * 9;       // 128

    unsigned* flags = g_flagsL[layer];

    const int cta   = blockIdx.x;
    const int group = cta >> 5;
    const int cidx  = cta & 31;
    const int j0    = cidx * 16;
    const int b0    = group * 8;
    const int wid   = tid >> 5;
    const int lane  = tid & 31;

    for (int i = tid; i < 64 * 128; i += SCAN_TPB) {
        int rl = i >> 7;
        int k4 = i & 127;
        int grow = (rl >> 4) * Hq + j0 + (rl & 15);
        *reinterpret_cast<float4*>(Wsh + rl * WS + k4 * 4) =
            *reinterpret_cast<const float4*>(Whh + (size_t)grow * Hq + k4 * 4);
    }
    if (tid < 128) csh[tid] = 0.f;
    __syncthreads();

    const int bl = tid >> 4;
    const int jj = tid & 15;

    float gxv0 = 0.f, gxv1 = 0.f, gxv2 = 0.f, gxv3 = 0.f;
    if (tid < 128) {
        const float* gp = gx + (size_t)(b0 + bl) * Sq * Gq + j0 + jj;
        gxv0 = gp[0]; gxv1 = gp[Hq]; gxv2 = gp[2 * Hq]; gxv3 = gp[3 * Hq];
    }

    const float* Ws0 = Wsh + lane * WS;
    const float* Ws1 = Wsh + (lane + 32) * WS;
    const int kw = wid * 64;
    const int sj = lane & 15;
    const int sb = lane >> 4;

    for (int t = 0; t < Sq; ++t) {
        const int cur = t & 1, nxt = cur ^ 1;

        if (t > 0) {
            {
                unsigned target = (unsigned)t;
                const unsigned* f = &flags[(group * 32 + lane) * 32];
                unsigned seen = 0u;
                do {
                    if (!seen) {
                        unsigned v;
                        asm volatile("ld.relaxed.gpu.global.u32 %0, [%1];"
                                     : "=r"(v) : "l"(f));
                        seen = (v == target) ? 1u : 0u;
                    }
                } while (__all_sync(0xffffffffu, seen) == 0);
            }

            {
                const float* hbase = g_h[cur] + (size_t)b0 * Hq + kw;
#pragma unroll
                for (int p = 0; p < 4; ++p) {
                    int b = sb + p * 2;
                    float4 v = __ldcg(reinterpret_cast<const float4*>(
                                          hbase + (size_t)b * Hq) + sj);
                    *reinterpret_cast<float4*>(hsh + b * HP + kw + sj * 4) = v;
                }
            }
            __syncwarp();

            {
                ull acc[2][8];
#pragma unroll
                for (int r = 0; r < 2; ++r)
#pragma unroll
                    for (int b = 0; b < 8; ++b) acc[r][b] = 0ull;
#pragma unroll
                for (int k4 = 0; k4 < 16; ++k4) {
                    int k = kw + k4 * 4;
                    ulonglong2 w0 = *reinterpret_cast<const ulonglong2*>(Ws0 + k);
                    ulonglong2 w1 = *reinterpret_cast<const ulonglong2*>(Ws1 + k);
#pragma unroll
                    for (int b = 0; b < 8; ++b) {
                        ulonglong2 hp =
                            *reinterpret_cast<const ulonglong2*>(hsh + b * HP + k);
                        FMA2(acc[0][b], hp.x, w0.x);
                        FMA2(acc[0][b], hp.y, w0.y);
                        FMA2(acc[1][b], hp.x, w1.x);
                        FMA2(acc[1][b], hp.y, w1.y);
                    }
                }
#pragma unroll
                for (int r = 0; r < 2; ++r)
#pragma unroll
                    for (int b = 0; b < 8; ++b) {
                        float lo, hi; UNPK2(lo, hi, acc[r][b]);
                        part[(wid * 64 + lane + r * 32) * 9 + b] = lo + hi;
                    }
            }
            __syncthreads();
        }

        if (tid < 128) {
            float s0 = 0.f, s1 = 0.f, s2 = 0.f, s3 = 0.f;
            if (t > 0) {
#pragma unroll
                for (int w = 0; w < 8; ++w) {
                    s0 += part[(w * 64 +      jj) * 9 + bl];
                    s1 += part[(w * 64 + 16 + jj) * 9 + bl];
                    s2 += part[(w * 64 + 32 + jj) * 9 + bl];
                    s3 += part[(w * 64 + 48 + jj) * 9 + bl];
                }
            }
            float si = fsigmoid(s0 + gxv0);
            float sf = fsigmoid(s1 + gxv1);
            float tg = ftanh(s2 + gxv2);
            float so = fsigmoid(s3 + gxv3);
            float c  = sf * csh[tid] + si * tg;
            csh[tid] = c;
            float hn = so * ftanh(c);
            int bglob = b0 + bl;
            g_h[nxt][(size_t)bglob * Hq + j0 + jj] = hn;

            asm volatile("bar.sync 1, 128;" ::: "memory");
            if (tid == 0) {
                unsigned val = (unsigned)(t + 1);
                asm volatile("membar.gl;" ::: "memory");
                asm volatile("st.release.gpu.global.u32 [%0], %1;"
                             :: "l"(&flags[cta * 32]), "r"(val) : "memory");
            }

            out[((size_t)bglob * Sq + t) * Hq + j0 + jj] = hn;
            int tn = (t + 1 < Sq) ? t + 1 : t;
            const float* gp = gx + ((size_t)bglob * Sq + tn) * Gq + j0 + jj;
            gxv0 = gp[0]; gxv1 = gp[Hq]; gxv2 = gp[2 * Hq]; gxv3 = gp[3 * Hq];
        }
    }

    // final publish: covers out[255] for gemm consumers (value > all targets)
    __syncthreads();
    if (tid == 0) {
        asm volatile("membar.gl;" ::: "memory");
        asm volatile("st.release.gpu.global.u32 [%0], %1;"
                     :: "l"(&flags[cta * 32]), "r"(300u) : "memory");
    }
}

// ---------------- softmax over sequence axis -----------------------------
__global__ void __launch_bounds__(256) softmax_kernel(
    const float* __restrict__ in, float* __restrict__ probs)
{
    int gw = (blockIdx.x * 256 + threadIdx.x) >> 5;
    int lane = threadIdx.x & 31;
    int bb = gw >> 9;
    int hh = gw & 511;
    const float* p = in + (size_t)bb * Sq * Hq + hh;
    float v[8];
    float mx = -3.4e38f;
#pragma unroll
    for (int i = 0; i < 8; ++i) {
        v[i] = p[(size_t)(lane + 32 * i) * Hq];
        mx = fmaxf(mx, v[i]);
    }
#pragma unroll
    for (int o = 16; o; o >>= 1) mx = fmaxf(mx, __shfl_xor_sync(0xffffffffu, mx, o));
    float sum = 0.f;
#pragma unroll
    for (int i = 0; i < 8; ++i) { v[i] = __expf(v[i] - mx); sum += v[i]; }
#pragma unroll
    for (int o = 16; o; o >>= 1) sum += __shfl_xor_sync(0xffffffffu, sum, o);
    float inv = 1.f / sum;
    float* q = probs + (size_t)bb * Sq * Hq + hh;
#pragma unroll
    for (int i = 0; i < 8; ++i) q[(size_t)(lane + 32 * i) * Hq] = v[i] * inv;
}

// ---------------- final FC ------------------------------------------------
__global__ void __launch_bounds__(256) fc_kernel(
    const float* __restrict__ probs, const float* __restrict__ Wfc,
    const float* __restrict__ bfc, float* __restrict__ out)
{
    int gw = (blockIdx.x * 256 + threadIdx.x) >> 5;
    int lane = threadIdx.x & 31;
    const float* p = probs + (size_t)gw * Hq;
    float a0 = 0.f, a1 = 0.f, a2 = 0.f, a3 = 0.f;
    for (int k = lane; k < Hq; k += 32) {
        float pv = p[k];
        a0 += pv * Wfc[k];
        a1 += pv * Wfc[Hq + k];
        a2 += pv * Wfc[2 * Hq + k];
        a3 += pv * Wfc[3 * Hq + k];
    }
#pragma unroll
    for (int o = 16; o; o >>= 1) {
        a0 += __shfl_xor_sync(0xffffffffu, a0, o);
        a1 += __shfl_xor_sync(0xffffffffu, a1, o);
        a2 += __shfl_xor_sync(0xffffffffu, a2, o);
        a3 += __shfl_xor_sync(0xffffffffu, a3, o);
    }
    if (lane == 0) {
        float4 r;
        r.x = a0 + bfc[0]; r.y = a1 + bfc[1];
        r.z = a2 + bfc[2]; r.w = a3 + bfc[3];
        *reinterpret_cast<float4*>(out + (size_t)gw * 4) = r;
    }
}

// ---------------- launcher -----------------------------------------------
extern "C" void kernel_launch(void* const* d_in, const int* in_sizes, int n_in,
                              void* d_out, int out_size)
{
    const float* x    = (const float*)d_in[0];
    const float* Wih0 = (const float*)d_in[1];
    const float* WihR = (const float*)d_in[2];
    const float* Whh  = (const float*)d_in[3];
    const float* bih  = (const float*)d_in[4];
    const float* bhh  = (const float*)d_in[5];
    const float* Wfc  = (const float*)d_in[6];
    const float* bfc  = (const float*)d_in[7];
    float* out = (float*)d_out;

    float *gxA, *gxB, *io0, *io1;
    cudaGetSymbolAddress((void**)&gxA, g_gxA);
    cudaGetSymbolAddress((void**)&gxB, g_gxB);
    cudaGetSymbolAddress((void**)&io0, g_io0);
    cudaGetSymbolAddress((void**)&io1, g_io1);

    cudaFuncSetAttribute(scan_gemm_kernel,
                         cudaFuncAttributeMaxDynamicSharedMemorySize,
                         SCAN_SMEM_BYTES);

    // layer-0 gemm (K=256) + flag zeroing
    gemm_kernel<<<dim3(Gq / 128, M_TOT / 128), 256>>>(
        x, Wih0, bih, bhh, gxA, Eq);

    const float* gin[4]  = {gxA, gxB, gxA, gxB};
    float*       gout[4] = {gxB, gxA, gxB, nullptr};   // gemm(l+1) target
    float*       sout[4] = {io0, io1, io0, io1};

    for (int l = 0; l < 4; ++l) {
        int ng = (l < 3) ? NGEMM : 0;
        const float* Wn  = (l < 3) ? (WihR + (size_t)l * Gq * Hq) : nullptr;
        const float* bn  = (l < 3) ? (bih + (size_t)(l + 1) * Gq) : nullptr;
        const float* bn2 = (l < 3) ? (bhh + (size_t)(l + 1) * Gq) : nullptr;
        scan_gemm_kernel<<<SCAN_NCTA + ng, SCAN_TPB, SCAN_SMEM_BYTES>>>(
            gin[l], Whh + (size_t)l * Gq * Hq, sout[l], l,
            Wn, bn, bn2, gout[l]);
    }

    softmax_kernel<<<2048, 256>>>(io1, gxA);
    fc_kernel<<<1024, 256>>>(gxA, Wfc, bfc, out);
}

// round 12
// speedup vs baseline: 1.0033x; 1.0033x over previous
#include <cuda_runtime.h>
#include <cstdint>

#define Bq 32
#define Sq 256
#define Eq 256
#define Hq 512
#define Gq 2048          // 4*H
#define M_TOT (Bq * Sq)  // 8192

#define SCAN_NCTA 128
#define SCAN_TPB  256
#define HP 132           // hsh row pad (floats)
#define WS 516           // Wsh row stride (floats)
#define NGEMM 1024       // co-scheduled gemm tiles (64 m-tiles x 16 n-tiles)

#define SCAN_SMEM_FLOATS (64 * WS + 8 * HP + 8 * 64 * 9 + 128)
#define SCAN_SMEM_BYTES  (SCAN_SMEM_FLOATS * 4)

typedef unsigned long long ull;

#define FMA2(acc, a, b) \
    asm("fma.rn.f32x2 %0, %1, %2, %0;" : "+l"(acc) : "l"(a), "l"(b))
#define DUP2(d, s) \
    asm("mov.b64 %0, {%1, %1};" : "=l"(d) : "f"(s))
#define UNPK2(lo, hi, v) \
    asm("mov.b64 {%0, %1}, %2;" : "=f"(lo), "=f"(hi) : "l"(v))

__device__ __forceinline__ float fsigmoid(float x) {
    return __fdividef(1.f, 1.f + __expf(-x));
}
__device__ __forceinline__ float ftanh(float x) {
    float e = __expf(2.f * x);
    return 1.f - __fdividef(2.f, e + 1.f);
}

// ---------------- device scratch (static, no allocation) ----------------
__device__ float g_gxA[M_TOT * Gq];      // gx ping
__device__ float g_gxB[M_TOT * Gq];      // gx pong
__device__ float g_io0[M_TOT * Hq];
__device__ float g_io1[M_TOT * Hq];
__device__ float g_h[2][Bq * Hq];
__device__ unsigned g_flagsL[4][SCAN_NCTA * 32];  // per-layer, 128B-padded slots

// ---------------- standalone layer-0 GEMM (also zeroes ALL flags) --------
__global__ void __launch_bounds__(256, 2) gemm_kernel(
    const float* __restrict__ A, const float* __restrict__ W,
    const float* __restrict__ bih, const float* __restrict__ bhh,
    float* __restrict__ C, int K)
{
    __shared__ float As[2][8][128];
    __shared__ float Bs[2][8][128];
    const int tid = threadIdx.x;

    // zero all layer flags once per replay (stream-ordered before co-kernels)
    if (blockIdx.x == 0 && blockIdx.y == 0) {
        unsigned* f = &g_flagsL[0][0];
        for (int i = tid; i < 4 * SCAN_NCTA * 32; i += 256) f[i] = 0u;
    }

    const int m0 = blockIdx.y * 128;
    const int n0 = blockIdx.x * 128;
    const int lr = tid >> 1;
    const int lk = (tid & 1) * 4;
    const int tx = tid & 15;
    const int ty = tid >> 4;

    ull acc2[8][4];
#pragma unroll
    for (int i = 0; i < 8; ++i)
#pragma unroll
        for (int j = 0; j < 4; ++j) acc2[i][j] = 0ull;

    const float* Ap = A + (size_t)(m0 + lr) * K + lk;
    const float* Wp = W + (size_t)(n0 + lr) * K + lk;
    float4 pa = *reinterpret_cast<const float4*>(Ap);
    float4 pb = *reinterpret_cast<const float4*>(Wp);

    As[0][lk + 0][lr] = pa.x; As[0][lk + 1][lr] = pa.y;
    As[0][lk + 2][lr] = pa.z; As[0][lk + 3][lr] = pa.w;
    Bs[0][lk + 0][lr] = pb.x; Bs[0][lk + 1][lr] = pb.y;
    Bs[0][lk + 2][lr] = pb.z; Bs[0][lk + 3][lr] = pb.w;
    __syncthreads();

    const int nk = K >> 3;
    for (int kt = 0; kt < nk; ++kt) {
        const int buf = kt & 1;
        if (kt + 1 < nk) {
            pa = *reinterpret_cast<const float4*>(Ap + (kt + 1) * 8);
            pb = *reinterpret_cast<const float4*>(Wp + (kt + 1) * 8);
        }
#pragma unroll
        for (int kk = 0; kk < 8; ++kk) {
            float4 a0 = *reinterpret_cast<const float4*>(&As[buf][kk][ty * 4]);
            float4 a1 = *reinterpret_cast<const float4*>(&As[buf][kk][64 + ty * 4]);
            ulonglong2 bb0 = *reinterpret_cast<const ulonglong2*>(&Bs[buf][kk][tx * 4]);
            ulonglong2 bb1 = *reinterpret_cast<const ulonglong2*>(&Bs[buf][kk][64 + tx * 4]);
            float am[8] = {a0.x, a0.y, a0.z, a0.w, a1.x, a1.y, a1.z, a1.w};
            ull bp0 = bb0.x, bp1 = bb0.y, bp2 = bb1.x, bp3 = bb1.y;
#pragma unroll
            for (int i = 0; i < 8; ++i) {
                ull a2; DUP2(a2, am[i]);
                FMA2(acc2[i][0], a2, bp0);
                FMA2(acc2[i][1], a2, bp1);
                FMA2(acc2[i][2], a2, bp2);
                FMA2(acc2[i][3], a2, bp3);
            }
        }
        if (kt + 1 < nk) {
            const int nb = buf ^ 1;
            As[nb][lk + 0][lr] = pa.x; As[nb][lk + 1][lr] = pa.y;
            As[nb][lk + 2][lr] = pa.z; As[nb][lk + 3][lr] = pa.w;
            Bs[nb][lk + 0][lr] = pb.x; Bs[nb][lk + 1][lr] = pb.y;
            Bs[nb][lk + 2][lr] = pb.z; Bs[nb][lk + 3][lr] = pb.w;
            __syncthreads();
        }
    }

    float acc[8][8];
#pragma unroll
    for (int i = 0; i < 8; ++i)
#pragma unroll
        for (int j = 0; j < 4; ++j)
            UNPK2(acc[i][2 * j], acc[i][2 * j + 1], acc2[i][j]);

    const int nc0 = n0 + tx * 4;
    const int nc1 = n0 + 64 + tx * 4;
    float bs0[4], bs1[4];
#pragma unroll
    for (int j = 0; j < 4; ++j) {
        bs0[j] = bih[nc0 + j] + bhh[nc0 + j];
        bs1[j] = bih[nc1 + j] + bhh[nc1 + j];
    }
#pragma unroll
    for (int i = 0; i < 8; ++i) {
        int m = m0 + ((i < 4) ? (ty * 4 + i) : (64 + ty * 4 + i - 4));
        float4 v0, v1;
        v0.x = acc[i][0] + bs0[0]; v0.y = acc[i][1] + bs0[1];
        v0.z = acc[i][2] + bs0[2]; v0.w = acc[i][3] + bs0[3];
        v1.x = acc[i][4] + bs1[0]; v1.y = acc[i][5] + bs1[1];
        v1.z = acc[i][6] + bs1[2]; v1.w = acc[i][7] + bs1[3];
        *reinterpret_cast<float4*>(C + (size_t)m * Gq + nc0) = v0;
        *reinterpret_cast<float4*>(C + (size_t)m * Gq + nc1) = v1;
    }
}

// ============== co-kernel: scan(layer) + flag-gated gemm(layer+1) ========
// bids 0..127: persistent scan CTAs (wave-1 resident, one per SM).
// bids 128+ : gemm tiles of NEXT layer's input GEMM; each polls scan
// progress flags (>= s0+129 covers out rows [s0, s0+128)) before running.
__global__ void __launch_bounds__(SCAN_TPB) scan_gemm_kernel(
    const float* __restrict__ gx,     // [b][s][2048]  this layer's gates
    const float* __restrict__ Whh,    // [2048][512]   this layer
    float* __restrict__ out,          // [b][s][512]   this layer's output
    int layer,
    const float* __restrict__ Wn,     // next layer Wih [2048][512] (or null)
    const float* __restrict__ bihn, const float* __restrict__ bhhn,
    float* __restrict__ gxn)          // next layer gx out
{
    extern __shared__ float sm[];
    const int tid = threadIdx.x;

    if (blockIdx.x >= SCAN_NCTA) {
        // ---------------- gemm role ----------------
        float* AsF = sm;               // [2][8][128]
        float* BsF = sm + 2048;        // [2][8][128]
        const int g  = blockIdx.x - SCAN_NCTA;
        const int s0 = (g < 512) ? 0 : 128;
        const int gg = g & 511;
        const int b  = gg >> 4;
        const int m0 = b * 256 + s0;
        const int n0 = (gg & 15) * 128;
        const int group = b >> 3;
        const unsigned target = (unsigned)(s0 + 129);

        if (tid < 32) {
            const unsigned* f = &g_flagsL[layer][(group * 32 + tid) * 32];
            unsigned v;
            do {
                asm volatile("ld.acquire.gpu.global.u32 %0, [%1];"
                             : "=r"(v) : "l"(f));
            } while (__all_sync(0xffffffffu, v >= target) == 0);
        }
        __syncthreads();

        const int K = Hq;              // 512
        const int lr = tid >> 1;
        const int lk = (tid & 1) * 4;
        const int tx = tid & 15;
        const int ty = tid >> 4;

        ull acc2[8][4];
#pragma unroll
        for (int i = 0; i < 8; ++i)
#pragma unroll
            for (int j = 0; j < 4; ++j) acc2[i][j] = 0ull;

        const float* Ap = out + (size_t)(m0 + lr) * K + lk;   // A = this layer's out
        const float* Wp = Wn + (size_t)(n0 + lr) * K + lk;
        float4 pa = *reinterpret_cast<const float4*>(Ap);
        float4 pb = *reinterpret_cast<const float4*>(Wp);

#define ASG(bf, r, c) AsF[(bf) * 1024 + (r) * 128 + (c)]
#define BSG(bf, r, c) BsF[(bf) * 1024 + (r) * 128 + (c)]
        ASG(0, lk + 0, lr) = pa.x; ASG(0, lk + 1, lr) = pa.y;
        ASG(0, lk + 2, lr) = pa.z; ASG(0, lk + 3, lr) = pa.w;
        BSG(0, lk + 0, lr) = pb.x; BSG(0, lk + 1, lr) = pb.y;
        BSG(0, lk + 2, lr) = pb.z; BSG(0, lk + 3, lr) = pb.w;
        __syncthreads();

        const int nk = K >> 3;
        for (int kt = 0; kt < nk; ++kt) {
            const int buf = kt & 1;
            if (kt + 1 < nk) {
                pa = *reinterpret_cast<const float4*>(Ap + (kt + 1) * 8);
                pb = *reinterpret_cast<const float4*>(Wp + (kt + 1) * 8);
            }
#pragma unroll
            for (int kk = 0; kk < 8; ++kk) {
                float4 a0 = *reinterpret_cast<const float4*>(&ASG(buf, kk, ty * 4));
                float4 a1 = *reinterpret_cast<const float4*>(&ASG(buf, kk, 64 + ty * 4));
                ulonglong2 bb0 = *reinterpret_cast<const ulonglong2*>(&BSG(buf, kk, tx * 4));
                ulonglong2 bb1 = *reinterpret_cast<const ulonglong2*>(&BSG(buf, kk, 64 + tx * 4));
                float am[8] = {a0.x, a0.y, a0.z, a0.w, a1.x, a1.y, a1.z, a1.w};
                ull bp0 = bb0.x, bp1 = bb0.y, bp2 = bb1.x, bp3 = bb1.y;
#pragma unroll
                for (int i = 0; i < 8; ++i) {
                    ull a2; DUP2(a2, am[i]);
                    FMA2(acc2[i][0], a2, bp0);
                    FMA2(acc2[i][1], a2, bp1);
                    FMA2(acc2[i][2], a2, bp2);
                    FMA2(acc2[i][3], a2, bp3);
                }
            }
            if (kt + 1 < nk) {
                const int nb = buf ^ 1;
                ASG(nb, lk + 0, lr) = pa.x; ASG(nb, lk + 1, lr) = pa.y;
                ASG(nb, lk + 2, lr) = pa.z; ASG(nb, lk + 3, lr) = pa.w;
                BSG(nb, lk + 0, lr) = pb.x; BSG(nb, lk + 1, lr) = pb.y;
                BSG(nb, lk + 2, lr) = pb.z; BSG(nb, lk + 3, lr) = pb.w;
                __syncthreads();
            }
        }
#undef ASG
#undef BSG

        float acc[8][8];
#pragma unroll
        for (int i = 0; i < 8; ++i)
#pragma unroll
            for (int j = 0; j < 4; ++j)
                UNPK2(acc[i][2 * j], acc[i][2 * j + 1], acc2[i][j]);

        const int nc0 = n0 + tx * 4;
        const int nc1 = n0 + 64 + tx * 4;
        float bs0[4], bs1[4];
#pragma unroll
        for (int j = 0; j < 4; ++j) {
            bs0[j] = bihn[nc0 + j] + bhhn[nc0 + j];
            bs1[j] = bihn[nc1 + j] + bhhn[nc1 + j];
        }
#pragma unroll
        for (int i = 0; i < 8; ++i) {
            int m = m0 + ((i < 4) ? (ty * 4 + i) : (64 + ty * 4 + i - 4));
            float4 v0, v1;
            v0.x = acc[i][0] + bs0[0]; v0.y = acc[i][1] + bs0[1];
            v0.z = acc[i][2] + bs0[2]; v0.w = acc[i][3] + bs0[3];
            v1.x = acc[i][4] + bs1[0]; v1.y = acc[i][5] + bs1[1];
            v1.z = acc[i][6] + bs1[2]; v1.w = acc[i][7] + bs1[3];
            *reinterpret_cast<float4*>(gxn + (size_t)m * Gq + nc0) = v0;
            *reinterpret_cast<float4*>(gxn + (size_t)m * Gq + nc1) = v1;
        }
        return;
    }

    // ---------------- scan role (R9-proven, per-layer flags) ----------------
    float* Wsh  = sm;                      // 64 * WS
    float* hsh  = Wsh + 64 * WS;           // 8 * HP
    float* part = hsh + 8 * HP;            // 8 * 64 * 9
    float* csh  = part + 8 * 64 * 9;       // 128

    unsigned* flags = g_flagsL[layer];

    const int cta   = blockIdx.x;
    const int group = cta >> 5;
    const int cidx  = cta & 31;
    const int j0    = cidx * 16;
    const int b0    = group * 8;
    const int wid   = tid >> 5;
    const int lane  = tid & 31;

    for (int i = tid; i < 64 * 128; i += SCAN_TPB) {
        int rl = i >> 7;
        int k4 = i & 127;
        int grow = (rl >> 4) * Hq + j0 + (rl & 15);
        *reinterpret_cast<float4*>(Wsh + rl * WS + k4 * 4) =
            *reinterpret_cast<const float4*>(Whh + (size_t)grow * Hq + k4 * 4);
    }
    if (tid < 128) csh[tid] = 0.f;
    __syncthreads();

    const int bl = tid >> 4;
    const int jj = tid & 15;

    float gxv0 = 0.f, gxv1 = 0.f, gxv2 = 0.f, gxv3 = 0.f;
    if (tid < 128) {
        const float* gp = gx + (size_t)(b0 + bl) * Sq * Gq + j0 + jj;
        gxv0 = gp[0]; gxv1 = gp[Hq]; gxv2 = gp[2 * Hq]; gxv3 = gp[3 * Hq];
    }

    const float* Ws0 = Wsh + lane * WS;
    const float* Ws1 = Wsh + (lane + 32) * WS;
    const int kw = wid * 64;
    const int sj = lane & 15;
    const int sb = lane >> 4;

    for (int t = 0; t < Sq; ++t) {
        const int cur = t & 1, nxt = cur ^ 1;

        if (t > 0) {
            {
                unsigned target = (unsigned)t;
                const unsigned* f = &flags[(group * 32 + lane) * 32];
                unsigned seen = 0u;
                do {
                    if (!seen) {
                        unsigned v;
                        asm volatile("ld.relaxed.gpu.global.u32 %0, [%1];"
                                     : "=r"(v) : "l"(f));
                        seen = (v == target) ? 1u : 0u;
                    }
                } while (__all_sync(0xffffffffu, seen) == 0);
            }

            {
                const float* hbase = g_h[cur] + (size_t)b0 * Hq + kw;
#pragma unroll
                for (int p = 0; p < 4; ++p) {
                    int b = sb + p * 2;
                    float4 v = __ldcg(reinterpret_cast<const float4*>(
                                          hbase + (size_t)b * Hq) + sj);
                    *reinterpret_cast<float4*>(hsh + b * HP + kw + sj * 4) = v;
                }
            }
            __syncwarp();

            {
                ull acc[2][8];
#pragma unroll
                for (int r = 0; r < 2; ++r)
#pragma unroll
                    for (int b = 0; b < 8; ++b) acc[r][b] = 0ull;
#pragma unroll
                for (int k4 = 0; k4 < 16; ++k4) {
                    int k = kw + k4 * 4;
                    ulonglong2 w0 = *reinterpret_cast<const ulonglong2*>(Ws0 + k);
                    ulonglong2 w1 = *reinterpret_cast<const ulonglong2*>(Ws1 + k);
#pragma unroll
                    for (int b = 0; b < 8; ++b) {
                        ulonglong2 hp =
                            *reinterpret_cast<const ulonglong2*>(hsh + b * HP + k);
                        FMA2(acc[0][b], hp.x, w0.x);
                        FMA2(acc[0][b], hp.y, w0.y);
                        FMA2(acc[1][b], hp.x, w1.x);
                        FMA2(acc[1][b], hp.y, w1.y);
                    }
                }
#pragma unroll
                for (int r = 0; r < 2; ++r)
#pragma unroll
                    for (int b = 0; b < 8; ++b) {
                        float lo, hi; UNPK2(lo, hi, acc[r][b]);
                        part[(wid * 64 + lane + r * 32) * 9 + b] = lo + hi;
                    }
            }
            __syncthreads();
        }

        if (tid < 128) {
            float s0 = 0.f, s1 = 0.f, s2 = 0.f, s3 = 0.f;
            if (t > 0) {
#pragma unroll
                for (int w = 0; w < 8; ++w) {
                    s0 += part[(w * 64 +      jj) * 9 + bl];
                    s1 += part[(w * 64 + 16 + jj) * 9 + bl];
                    s2 += part[(w * 64 + 32 + jj) * 9 + bl];
                    s3 += part[(w * 64 + 48 + jj) * 9 + bl];
                }
            }
            float si = fsigmoid(s0 + gxv0);
            float sf = fsigmoid(s1 + gxv1);
            float tg = ftanh(s2 + gxv2);
            float so = fsigmoid(s3 + gxv3);
            float c  = sf * csh[tid] + si * tg;
            csh[tid] = c;
            float hn = so * ftanh(c);
            int bglob = b0 + bl;
            g_h[nxt][(size_t)bglob * Hq + j0 + jj] = hn;

            asm volatile("bar.sync 1, 128;" ::: "memory");
            if (tid == 0) {
                unsigned val = (unsigned)(t + 1);
                asm volatile("membar.gl;" ::: "memory");
                asm volatile("st.release.gpu.global.u32 [%0], %1;"
                             :: "l"(&flags[cta * 32]), "r"(val) : "memory");
            }

            out[((size_t)bglob * Sq + t) * Hq + j0 + jj] = hn;
            int tn = (t + 1 < Sq) ? t + 1 : t;
            const float* gp = gx + ((size_t)bglob * Sq + tn) * Gq + j0 + jj;
            gxv0 = gp[0]; gxv1 = gp[Hq]; gxv2 = gp[2 * Hq]; gxv3 = gp[3 * Hq];
        }
    }

    // final publish: covers out[255] for gemm consumers (value > all targets)
    __syncthreads();
    if (tid == 0) {
        asm volatile("membar.gl;" ::: "memory");
        asm volatile("st.release.gpu.global.u32 [%0], %1;"
                     :: "l"(&flags[cta * 32]), "r"(300u) : "memory");
    }
}

// ---------------- softmax over sequence axis -----------------------------
__global__ void __launch_bounds__(256) softmax_kernel(
    const float* __restrict__ in, float* __restrict__ probs)
{
    int gw = (blockIdx.x * 256 + threadIdx.x) >> 5;
    int lane = threadIdx.x & 31;
    int bb = gw >> 9;
    int hh = gw & 511;
    const float* p = in + (size_t)bb * Sq * Hq + hh;
    float v[8];
    float mx = -3.4e38f;
#pragma unroll
    for (int i = 0; i < 8; ++i) {
        v[i] = p[(size_t)(lane + 32 * i) * Hq];
        mx = fmaxf(mx, v[i]);
    }
#pragma unroll
    for (int o = 16; o; o >>= 1) mx = fmaxf(mx, __shfl_xor_sync(0xffffffffu, mx, o));
    float sum = 0.f;
#pragma unroll
    for (int i = 0; i < 8; ++i) { v[i] = __expf(v[i] - mx); sum += v[i]; }
#pragma unroll
    for (int o = 16; o; o >>= 1) sum += __shfl_xor_sync(0xffffffffu, sum, o);
    float inv = 1.f / sum;
    float* q = probs + (size_t)bb * Sq * Hq + hh;
#pragma unroll
    for (int i = 0; i < 8; ++i) q[(size_t)(lane + 32 * i) * Hq] = v[i] * inv;
}

// ---------------- final FC ------------------------------------------------
__global__ void __launch_bounds__(256) fc_kernel(
    const float* __restrict__ probs, const float* __restrict__ Wfc,
    const float* __restrict__ bfc, float* __restrict__ out)
{
    int gw = (blockIdx.x * 256 + threadIdx.x) >> 5;
    int lane = threadIdx.x & 31;
    const float* p = probs + (size_t)gw * Hq;
    float a0 = 0.f, a1 = 0.f, a2 = 0.f, a3 = 0.f;
    for (int k = lane; k < Hq; k += 32) {
        float pv = p[k];
        a0 += pv * Wfc[k];
        a1 += pv * Wfc[Hq + k];
        a2 += pv * Wfc[2 * Hq + k];
        a3 += pv * Wfc[3 * Hq + k];
    }
#pragma unroll
    for (int o = 16; o; o >>= 1) {
        a0 += __shfl_xor_sync(0xffffffffu, a0, o);
        a1 += __shfl_xor_sync(0xffffffffu, a1, o);
        a2 += __shfl_xor_sync(0xffffffffu, a2, o);
        a3 += __shfl_xor_sync(0xffffffffu, a3, o);
    }
    if (lane == 0) {
        float4 r;
        r.x = a0 + bfc[0]; r.y = a1 + bfc[1];
        r.z = a2 + bfc[2]; r.w = a3 + bfc[3];
        *reinterpret_cast<float4*>(out + (size_t)gw * 4) = r;
    }
}

// ---------------- launcher -----------------------------------------------
extern "C" void kernel_launch(void* const* d_in, const int* in_sizes, int n_in,
                              void* d_out, int out_size)
{
    const float* x    = (const float*)d_in[0];
    const float* Wih0 = (const float*)d_in[1];
    const float* WihR = (const float*)d_in[2];
    const float* Whh  = (const float*)d_in[3];
    const float* bih  = (const float*)d_in[4];
    const float* bhh  = (const float*)d_in[5];
    const float* Wfc  = (const float*)d_in[6];
    const float* bfc  = (const float*)d_in[7];
    float* out = (float*)d_out;

    float *gxA, *gxB, *io0, *io1;
    cudaGetSymbolAddress((void**)&gxA, g_gxA);
    cudaGetSymbolAddress((void**)&gxB, g_gxB);
    cudaGetSymbolAddress((void**)&io0, g_io0);
    cudaGetSymbolAddress((void**)&io1, g_io1);

    cudaFuncSetAttribute(scan_gemm_kernel,
                         cudaFuncAttributeMaxDynamicSharedMemorySize,
                         SCAN_SMEM_BYTES);

    // layer-0 gemm (K=256) + flag zeroing
    gemm_kernel<<<dim3(Gq / 128, M_TOT / 128), 256>>>(
        x, Wih0, bih, bhh, gxA, Eq);

    const float* gin[4]  = {gxA, gxB, gxA, gxB};
    float*       gout[4] = {gxB, gxA, gxB, nullptr};   // gemm(l+1) target
    float*       sout[4] = {io0, io1, io0, io1};

    for (int l = 0; l < 4; ++l) {
        int ng = (l < 3) ? NGEMM : 0;
        const float* Wn  = (l < 3) ? (WihR + (size_t)l * Gq * Hq) : nullptr;
        const float* bn  = (l < 3) ? (bih + (size_t)(l + 1) * Gq) : nullptr;
        const float* bn2 = (l < 3) ? (bhh + (size_t)(l + 1) * Gq) : nullptr;
        scan_gemm_kernel<<<SCAN_NCTA + ng, SCAN_TPB, SCAN_SMEM_BYTES>>>(
            gin[l], Whh + (size_t)l * Gq * Hq, sout[l], l,
            Wn, bn, bn2, gout[l]);
    }

    softmax_kernel<<<2048, 256>>>(io1, gxA);
    fc_kernel<<<1024, 256>>>(gxA, Wfc, bfc, out);
}